// round 8
// baseline (speedup 1.0000x reference)
#include <cuda_runtime.h>
#include <cuda_fp16.h>

// SmileMoENorm — exact R6 structure (packed-fp16 affine + PDL + streaming
// hints, one warp per token, full row single-read into v[8]) with registers
// capped at 48 (__launch_bounds__(256,5)) to lift occupancy 32->40 warps/SM.
//
// R7 taught: 256-bit accesses double pk-table L1 wavefronts (L1 48->66%) —
// reverted. R5 taught: occupancy via x re-reads loses. This buys occupancy
// purely by register diet; the single-global-read structure is untouched.

#define N_TOKENS    131072
#define HIDDEN      1024
#define NUM_EXPERTS 8
#define H4          (HIDDEN / 4)
#define EPS         1e-5f

__device__ __half2 d_pk[NUM_EXPERTS * HIDDEN];   // (gamma, beta) per element

// ---- pre-pass: pack gamma/beta into fp16 ----------------------------------
__global__ void k_pack(const float* __restrict__ gamma,
                       const float* __restrict__ beta) {
    const int i = blockIdx.x * blockDim.x + threadIdx.x;   // 0..8191
    d_pk[i] = __floats2half2_rn(gamma[i], beta[i]);
}

// ------------------------------------------------------------- main kernel
__global__ __launch_bounds__(256, 5)
void smile_moe_norm_kernel(const float4* __restrict__ x,
                           const float4* __restrict__ logits4,   // [N,2] float4
                           float4* __restrict__ out) {
    const int warp_in_block = threadIdx.x >> 5;
    const int lane          = threadIdx.x & 31;
    const int token         = blockIdx.x * (blockDim.x >> 5) + warp_in_block;

    // ---- router: top-2 of 8 logits, renormalized softmax weights ----------
    const float4 la = __ldg(&logits4[token * 2 + 0]);
    const float4 lb = __ldg(&logits4[token * 2 + 1]);
    float l[NUM_EXPERTS] = { la.x, la.y, la.z, la.w, lb.x, lb.y, lb.z, lb.w };

    float best = l[0], second = -3.4e38f;
    int   e0 = 0,     e1 = 0;
    #pragma unroll
    for (int i = 1; i < NUM_EXPERTS; i++) {
        float v = l[i];
        if (v > best)        { second = best; e1 = e0; best = v; e0 = i; }
        else if (v > second) { second = v; e1 = i; }
    }
    const float t  = __expf(second - best);     // full-softmax denom cancels
    const float w0 = 1.0f / (1.0f + t);
    const float w1 = 1.0f - w0;
    const __half2 w0h = __float2half2_rn(w0);
    const __half2 w1h = __float2half2_rn(w1);

    // ---- pass over row: registers + warp reduction (streaming loads) -------
    const float4* xr = x + (size_t)token * H4;
    float4 v[8];
    float sum = 0.0f, sq = 0.0f;
    #pragma unroll
    for (int k = 0; k < 8; k++) {
        v[k] = __ldcs(&xr[lane + 32 * k]);      // touch-once: evict-first
        sum += v[k].x + v[k].y + v[k].z + v[k].w;
        sq = fmaf(v[k].x, v[k].x, sq); sq = fmaf(v[k].y, v[k].y, sq);
        sq = fmaf(v[k].z, v[k].z, sq); sq = fmaf(v[k].w, v[k].w, sq);
    }
    #pragma unroll
    for (int off = 16; off > 0; off >>= 1) {
        sum += __shfl_xor_sync(0xFFFFFFFFu, sum, off);
        sq  += __shfl_xor_sync(0xFFFFFFFFu, sq,  off);
    }
    const float mean = sum * (1.0f / HIDDEN);
    const float var  = fmaf(-mean, mean, sq * (1.0f / HIDDEN));
    const float rstd = rsqrtf(var + EPS);
    const float mr   = -mean * rstd;            // normed = x*rstd + mr

    // PDL: d_pk is written by k_pack; wait for it only now (hidden latency).
    cudaGridDependencySynchronize();

    // ---- epilogue: packed-fp16 blended affine + streaming store -------------
    const __half2* pk0 = d_pk + e0 * HIDDEN;
    const __half2* pk1 = d_pk + e1 * HIDDEN;
    float4* orow = out + (size_t)token * H4;

    #pragma unroll
    for (int k = 0; k < 8; k++) {
        const int h4 = lane + 32 * k;           // float4 index
        const int h  = 4 * h4;                  // element index
        const uint4 r0 = *(const uint4*)(pk0 + h);
        const uint4 r1 = *(const uint4*)(pk1 + h);

        const float nx = fmaf(v[k].x, rstd, mr);
        const float ny = fmaf(v[k].y, rstd, mr);
        const float nz = fmaf(v[k].z, rstd, mr);
        const float nw = fmaf(v[k].w, rstd, mr);

        __half2 a, b; float2 fb; float4 o;
        a = *(const __half2*)&r0.x; b = *(const __half2*)&r1.x;
        fb = __half22float2(__hfma2(a, w0h, __hmul2(b, w1h)));
        o.x = fmaf(nx, fb.x, fb.y);

        a = *(const __half2*)&r0.y; b = *(const __half2*)&r1.y;
        fb = __half22float2(__hfma2(a, w0h, __hmul2(b, w1h)));
        o.y = fmaf(ny, fb.x, fb.y);

        a = *(const __half2*)&r0.z; b = *(const __half2*)&r1.z;
        fb = __half22float2(__hfma2(a, w0h, __hmul2(b, w1h)));
        o.z = fmaf(nz, fb.x, fb.y);

        a = *(const __half2*)&r0.w; b = *(const __half2*)&r1.w;
        fb = __half22float2(__hfma2(a, w0h, __hmul2(b, w1h)));
        o.w = fmaf(nw, fb.x, fb.y);

        __stcs(&orow[h4], o);                   // streaming store
    }
}

// ------------------------------------------------------------------ launch
extern "C" void kernel_launch(void* const* d_in, const int* in_sizes, int n_in,
                              void* d_out, int out_size) {
    const float4* x       = (const float4*)d_in[0];  // hidden_states [N, H]
    const float4* logits4 = (const float4*)d_in[1];  // router_logits [N, 8]
    const float*  gamma   = (const float*)d_in[2];   // [E, H]
    const float*  beta    = (const float*)d_in[3];   // [E, H]
    float4* out           = (float4*)d_out;

    k_pack<<<(NUM_EXPERTS * HIDDEN) / 256, 256>>>(gamma, beta);

    cudaLaunchConfig_t cfg = {};
    cfg.gridDim  = dim3(N_TOKENS / 8, 1, 1);         // 8 warps/block
    cfg.blockDim = dim3(256, 1, 1);
    cudaLaunchAttribute attr[1];
    attr[0].id = cudaLaunchAttributeProgrammaticStreamSerialization;
    attr[0].val.programmaticStreamSerializationAllowed = 1;
    cfg.attrs = attr;
    cfg.numAttrs = 1;
    cudaLaunchKernelEx(&cfg, smile_moe_norm_kernel, x, logits4, out);
}

// round 9
// speedup vs baseline: 1.0024x; 1.0024x over previous
#include <cuda_runtime.h>
#include <cuda_fp16.h>

// SmileMoENorm — R6 main kernel EXACTLY (proven optimum: 56 regs, 32 warps/SM,
// packed-fp16 affine table, .cs streaming hints) + tightened PDL plumbing:
//
//  (a) k_pack calls cudaTriggerProgrammaticLaunchCompletion() at its top, so
//      the main grid's launch overlaps k_pack's execution entirely; the
//      epilogue gridsync still orders d_pk visibility.
//  (b) k_pack itself carries the PDL attr: during graph replay it overlaps
//      the previous iteration's main-kernel tail. Benign race: it rewrites
//      d_pk with bitwise-identical values (same gamma/beta every replay).
//  (c) k_pack vectorized to 8 blocks (float4-in, half2x4-out).
//
// R5/R7/R8 established: main kernel is HBM-turnaround-bound at ~83% DRAM;
// occupancy/width changes only regress it. Do not touch its structure.

#define N_TOKENS    131072
#define HIDDEN      1024
#define NUM_EXPERTS 8
#define H4          (HIDDEN / 4)
#define EPS         1e-5f

__device__ __half2 d_pk[NUM_EXPERTS * HIDDEN];   // (gamma, beta) per element

// ---- pre-pass: pack gamma/beta into fp16 (8 blocks, vectorized) -----------
__global__ void k_pack(const float4* __restrict__ gamma4,
                       const float4* __restrict__ beta4) {
    // Fire the dependent (main) grid's launch immediately; our writes are
    // ordered for it by its cudaGridDependencySynchronize().
    cudaTriggerProgrammaticLaunchCompletion();
    const int i = blockIdx.x * blockDim.x + threadIdx.x;   // 0..2047
    const float4 g = gamma4[i];
    const float4 b = beta4[i];
    __half2* dst = d_pk + i * 4;
    dst[0] = __floats2half2_rn(g.x, b.x);
    dst[1] = __floats2half2_rn(g.y, b.y);
    dst[2] = __floats2half2_rn(g.z, b.z);
    dst[3] = __floats2half2_rn(g.w, b.w);
}

// ------------------------------------------------------------- main kernel
__global__ __launch_bounds__(256, 4)
void smile_moe_norm_kernel(const float4* __restrict__ x,
                           const float4* __restrict__ logits4,   // [N,2] float4
                           float4* __restrict__ out) {
    const int warp_in_block = threadIdx.x >> 5;
    const int lane          = threadIdx.x & 31;
    const int token         = blockIdx.x * (blockDim.x >> 5) + warp_in_block;

    // ---- router: top-2 of 8 logits, renormalized softmax weights ----------
    const float4 la = __ldg(&logits4[token * 2 + 0]);
    const float4 lb = __ldg(&logits4[token * 2 + 1]);
    float l[NUM_EXPERTS] = { la.x, la.y, la.z, la.w, lb.x, lb.y, lb.z, lb.w };

    float best = l[0], second = -3.4e38f;
    int   e0 = 0,     e1 = 0;
    #pragma unroll
    for (int i = 1; i < NUM_EXPERTS; i++) {
        float v = l[i];
        if (v > best)        { second = best; e1 = e0; best = v; e0 = i; }
        else if (v > second) { second = v; e1 = i; }
    }
    const float t  = __expf(second - best);     // full-softmax denom cancels
    const float w0 = 1.0f / (1.0f + t);
    const float w1 = 1.0f - w0;
    const __half2 w0h = __float2half2_rn(w0);
    const __half2 w1h = __float2half2_rn(w1);

    // ---- pass over row: registers + warp reduction (streaming loads) -------
    const float4* xr = x + (size_t)token * H4;
    float4 v[8];
    float sum = 0.0f, sq = 0.0f;
    #pragma unroll
    for (int k = 0; k < 8; k++) {
        v[k] = __ldcs(&xr[lane + 32 * k]);      // touch-once: evict-first
        sum += v[k].x + v[k].y + v[k].z + v[k].w;
        sq = fmaf(v[k].x, v[k].x, sq); sq = fmaf(v[k].y, v[k].y, sq);
        sq = fmaf(v[k].z, v[k].z, sq); sq = fmaf(v[k].w, v[k].w, sq);
    }
    #pragma unroll
    for (int off = 16; off > 0; off >>= 1) {
        sum += __shfl_xor_sync(0xFFFFFFFFu, sum, off);
        sq  += __shfl_xor_sync(0xFFFFFFFFu, sq,  off);
    }
    const float mean = sum * (1.0f / HIDDEN);
    const float var  = fmaf(-mean, mean, sq * (1.0f / HIDDEN));
    const float rstd = rsqrtf(var + EPS);
    const float mr   = -mean * rstd;            // normed = x*rstd + mr

    // PDL: d_pk is written by k_pack; wait for it only now (latency hidden).
    cudaGridDependencySynchronize();

    // ---- epilogue: packed-fp16 blended affine + streaming store -------------
    const __half2* pk0 = d_pk + e0 * HIDDEN;
    const __half2* pk1 = d_pk + e1 * HIDDEN;
    float4* orow = out + (size_t)token * H4;

    #pragma unroll
    for (int k = 0; k < 8; k++) {
        const int h4 = lane + 32 * k;           // float4 index
        const int h  = 4 * h4;                  // element index
        const uint4 r0 = *(const uint4*)(pk0 + h);
        const uint4 r1 = *(const uint4*)(pk1 + h);

        const float nx = fmaf(v[k].x, rstd, mr);
        const float ny = fmaf(v[k].y, rstd, mr);
        const float nz = fmaf(v[k].z, rstd, mr);
        const float nw = fmaf(v[k].w, rstd, mr);

        __half2 a, b; float2 fb; float4 o;
        a = *(const __half2*)&r0.x; b = *(const __half2*)&r1.x;
        fb = __half22float2(__hfma2(a, w0h, __hmul2(b, w1h)));
        o.x = fmaf(nx, fb.x, fb.y);

        a = *(const __half2*)&r0.y; b = *(const __half2*)&r1.y;
        fb = __half22float2(__hfma2(a, w0h, __hmul2(b, w1h)));
        o.y = fmaf(ny, fb.x, fb.y);

        a = *(const __half2*)&r0.z; b = *(const __half2*)&r1.z;
        fb = __half22float2(__hfma2(a, w0h, __hmul2(b, w1h)));
        o.z = fmaf(nz, fb.x, fb.y);

        a = *(const __half2*)&r0.w; b = *(const __half2*)&r1.w;
        fb = __half22float2(__hfma2(a, w0h, __hmul2(b, w1h)));
        o.w = fmaf(nw, fb.x, fb.y);

        __stcs(&orow[h4], o);                   // streaming store
    }
}

// ------------------------------------------------------------------ launch
extern "C" void kernel_launch(void* const* d_in, const int* in_sizes, int n_in,
                              void* d_out, int out_size) {
    const float4* x       = (const float4*)d_in[0];  // hidden_states [N, H]
    const float4* logits4 = (const float4*)d_in[1];  // router_logits [N, 8]
    const float4* gamma4  = (const float4*)d_in[2];  // [E, H]
    const float4* beta4   = (const float4*)d_in[3];  // [E, H]
    float4* out           = (float4*)d_out;

    cudaLaunchAttribute attr[1];
    attr[0].id = cudaLaunchAttributeProgrammaticStreamSerialization;
    attr[0].val.programmaticStreamSerializationAllowed = 1;

    // k_pack: 2048 threads, PDL so replay i+1's pack overlaps replay i's tail
    // (benign: rewrites identical bytes).
    cudaLaunchConfig_t cfgp = {};
    cfgp.gridDim  = dim3(8, 1, 1);
    cfgp.blockDim = dim3(256, 1, 1);
    cfgp.attrs = attr;
    cfgp.numAttrs = 1;
    cudaLaunchKernelEx(&cfgp, k_pack, gamma4, beta4);

    // main kernel: PDL; k_pack's early trigger lets this launch immediately.
    cudaLaunchConfig_t cfg = {};
    cfg.gridDim  = dim3(N_TOKENS / 8, 1, 1);         // 8 warps/block
    cfg.blockDim = dim3(256, 1, 1);
    cfg.attrs = attr;
    cfg.numAttrs = 1;
    cudaLaunchKernelEx(&cfg, smile_moe_norm_kernel, x, logits4, out);
}